// round 1
// baseline (speedup 1.0000x reference)
#include <cuda_runtime.h>

// AttentionStem: per-pixel 4x4 local window attention.
// B=4, IC=3, OC=64, H=W=128, KS=4, PAD=2, M=4.
//
// Structure exploited:
//  - emb softmax over M depends only on (m, window-position ij) -> collapse the
//    M value branches into 16 precomputed 64x3 matrices Wv[ij] (prep kernel).
//  - Per pixel: load the 4x4x3 padded window into registers (via a per-row
//    shared tile), then for each of 64 channels do tiny dot products + softmax.
//  - Logits q*k are small -> softmax without max subtraction; fold log2(e)
//    into q and use ex2.approx directly (1 MUFU per exp).
//  - Use packed fp32x2 (fma.rn.f32x2 / mul / add) over window-position pairs
//    to halve FMA-pipe instruction count.

typedef unsigned long long u64;

#define LOG2E 1.4426950408889634f

__device__ __forceinline__ u64 pk2(float lo, float hi) {
    u64 r; asm("mov.b64 %0,{%1,%2};" : "=l"(r) : "f"(lo), "f"(hi)); return r;
}
__device__ __forceinline__ void upk2(u64 a, float& lo, float& hi) {
    asm("mov.b64 {%0,%1},%2;" : "=f"(lo), "=f"(hi) : "l"(a));
}
__device__ __forceinline__ u64 fma2_(u64 a, u64 b, u64 c) {
    u64 r; asm("fma.rn.f32x2 %0,%1,%2,%3;" : "=l"(r) : "l"(a), "l"(b), "l"(c)); return r;
}
__device__ __forceinline__ u64 mul2_(u64 a, u64 b) {
    u64 r; asm("mul.rn.f32x2 %0,%1,%2;" : "=l"(r) : "l"(a), "l"(b)); return r;
}
__device__ __forceinline__ u64 add2_(u64 a, u64 b) {
    u64 r; asm("add.rn.f32x2 %0,%1,%2;" : "=l"(r) : "l"(a), "l"(b)); return r;
}
__device__ __forceinline__ float ex2_(float x) {
    float r; asm("ex2.approx.f32 %0,%1;" : "=f"(r) : "f"(x)); return r;
}

// Precomputed mixed value weights: [o][c][pair p][lane s] where ij = 2p+s.
__device__ float g_wv[64 * 3 * 8 * 2];

__global__ void prep_kernel(const float* __restrict__ value_w,
                            const float* __restrict__ emb_a,
                            const float* __restrict__ emb_b,
                            const float* __restrict__ emb_mix) {
    __shared__ float emb[4][16];   // [m][ij]
    int t = threadIdx.x;
    if (t < 16) {
        int i = t >> 2, j = t & 3;
        float lg[4];
#pragma unroll
        for (int m = 0; m < 4; m++) {
            float la = 0.f, lb = 0.f;
            for (int o = 0; o < 64; o++) {
                float em = emb_mix[m * 64 + o];
                la += em * emb_a[o * 4 + i];
                lb += em * emb_b[o * 4 + j];
            }
            lg[m] = la + lb;
        }
        float mx = fmaxf(fmaxf(lg[0], lg[1]), fmaxf(lg[2], lg[3]));
        float e[4], s = 0.f;
#pragma unroll
        for (int m = 0; m < 4; m++) { e[m] = expf(lg[m] - mx); s += e[m]; }
#pragma unroll
        for (int m = 0; m < 4; m++) emb[m][t] = e[m] / s;
    }
    __syncthreads();
    for (int idx = t; idx < 1536; idx += blockDim.x) {
        int o = idx / 24, rem = idx % 24, c = rem / 8, p = rem % 8;
#pragma unroll
        for (int s = 0; s < 2; s++) {
            int ij = 2 * p + s;
            float acc = 0.f;
#pragma unroll
            for (int m = 0; m < 4; m++)
                acc += emb[m][ij] * value_w[(m * 64 + o) * 3 + c];
            g_wv[idx * 2 + s] = acc;
        }
    }
}

__global__ __launch_bounds__(128)
void attn_kernel(const float* __restrict__ x,
                 const float* __restrict__ key_w,
                 const float* __restrict__ query_w,
                 float* __restrict__ out) {
    __shared__ float sh_x[3][4][132];  // [c][window row][padded col]
    __shared__ float sh_kw[64 * 3];
    __shared__ float sh_qw[64 * 3];
    __shared__ u64   sh_wv[64 * 3 * 8];

    int tid = threadIdx.x;
    int b = blockIdx.x >> 7;
    int h = blockIdx.x & 127;

    // Load padded x tile: original rows h-2..h+1, cols -2..129.
    for (int idx = tid; idx < 3 * 4 * 132; idx += 128) {
        int c = idx / 528, rem = idx % 528, r = rem / 132, cc = rem % 132;
        int hr = h - 2 + r, wc = cc - 2;
        float v = 0.f;
        if (hr >= 0 && hr < 128 && wc >= 0 && wc < 128)
            v = x[((b * 3 + c) * 128 + hr) * 128 + wc];
        sh_x[c][r][cc] = v;
    }
    for (int idx = tid; idx < 192; idx += 128) {
        sh_kw[idx] = key_w[idx];
        sh_qw[idx] = query_w[idx];
    }
    {
        const u64* gw = (const u64*)g_wv;
        for (int idx = tid; idx < 1536; idx += 128) sh_wv[idx] = gw[idx];
    }
    __syncthreads();

    int w = tid;

    // Window into registers, packed by window-position pairs (same i, adjacent j).
    u64 wp[3][8];
    float ctr[3];
#pragma unroll
    for (int c = 0; c < 3; c++) {
#pragma unroll
        for (int p = 0; p < 8; p++) {
            int i = p >> 1, j0 = (p & 1) * 2;
            wp[c][p] = pk2(sh_x[c][i][w + j0], sh_x[c][i][w + j0 + 1]);
        }
        ctr[c] = sh_x[c][2][w + 2];
    }

    float* outp = out + ((b * 64) * 128 + h) * 128 + w;

#pragma unroll 2
    for (int o = 0; o < 64; o++) {
        float q = sh_qw[o * 3] * ctr[0] + sh_qw[o * 3 + 1] * ctr[1] + sh_qw[o * 3 + 2] * ctr[2];
        q *= LOG2E;
        u64 qq  = pk2(q, q);
        float k0 = sh_kw[o * 3], k1 = sh_kw[o * 3 + 1], k2w = sh_kw[o * 3 + 2];
        u64 kw0 = pk2(k0, k0);
        u64 kw1 = pk2(k1, k1);
        u64 kw2 = pk2(k2w, k2w);
        const u64* wv = sh_wv + o * 24;

        u64 acc = pk2(0.f, 0.f);
        u64 ss  = pk2(0.f, 0.f);
#pragma unroll
        for (int p = 0; p < 8; p++) {
            u64 kk = fma2_(kw0, wp[0][p], fma2_(kw1, wp[1][p], mul2_(kw2, wp[2][p])));
            u64 l2 = mul2_(qq, kk);
            float l0, l1; upk2(l2, l0, l1);
            u64 e2 = pk2(ex2_(l0), ex2_(l1));
            u64 v2 = fma2_(wv[p], wp[0][p],
                     fma2_(wv[8 + p], wp[1][p],
                     mul2_(wv[16 + p], wp[2][p])));
            acc = fma2_(e2, v2, acc);
            ss  = add2_(e2, ss);
        }
        float a0, a1, s0, s1;
        upk2(acc, a0, a1);
        upk2(ss, s0, s1);
        outp[o * 16384] = __fdividef(a0 + a1, s0 + s1);
    }
}

extern "C" void kernel_launch(void* const* d_in, const int* in_sizes, int n_in,
                              void* d_out, int out_size) {
    const float* x       = (const float*)d_in[0];
    const float* key_w   = (const float*)d_in[1];
    const float* query_w = (const float*)d_in[2];
    const float* value_w = (const float*)d_in[3];
    const float* emb_a   = (const float*)d_in[4];
    const float* emb_b   = (const float*)d_in[5];
    const float* emb_mix = (const float*)d_in[6];
    float* out = (float*)d_out;

    prep_kernel<<<1, 256>>>(value_w, emb_a, emb_b, emb_mix);
    attn_kernel<<<512, 128>>>(x, key_w, query_w, out);
}

// round 2
// speedup vs baseline: 1.7992x; 1.7992x over previous
#include <cuda_runtime.h>

// AttentionStem: per-pixel 4x4 local window attention.
// B=4, IC=3, OC=64, H=W=128, KS=4, PAD=2, M=4.
//
// R2 change vs R1: grid 512 -> 2048 (each block handles 16 of 64 output
// channels) to fix under-occupancy (18% -> ~37%); fold q into key weights
// to drop one packed mul per window pair.

typedef unsigned long long u64;

#define LOG2E 1.4426950408889634f

__device__ __forceinline__ u64 pk2(float lo, float hi) {
    u64 r; asm("mov.b64 %0,{%1,%2};" : "=l"(r) : "f"(lo), "f"(hi)); return r;
}
__device__ __forceinline__ void upk2(u64 a, float& lo, float& hi) {
    asm("mov.b64 {%0,%1},%2;" : "=f"(lo), "=f"(hi) : "l"(a));
}
__device__ __forceinline__ u64 fma2_(u64 a, u64 b, u64 c) {
    u64 r; asm("fma.rn.f32x2 %0,%1,%2,%3;" : "=l"(r) : "l"(a), "l"(b), "l"(c)); return r;
}
__device__ __forceinline__ u64 mul2_(u64 a, u64 b) {
    u64 r; asm("mul.rn.f32x2 %0,%1,%2;" : "=l"(r) : "l"(a), "l"(b)); return r;
}
__device__ __forceinline__ u64 add2_(u64 a, u64 b) {
    u64 r; asm("add.rn.f32x2 %0,%1,%2;" : "=l"(r) : "l"(a), "l"(b)); return r;
}
__device__ __forceinline__ float ex2_(float x) {
    float r; asm("ex2.approx.f32 %0,%1;" : "=f"(r) : "f"(x)); return r;
}

// Precomputed mixed value weights: [o][c][pair p][lane s] where ij = 2p+s.
__device__ float g_wv[64 * 3 * 8 * 2];

__global__ void prep_kernel(const float* __restrict__ value_w,
                            const float* __restrict__ emb_a,
                            const float* __restrict__ emb_b,
                            const float* __restrict__ emb_mix) {
    __shared__ float emb[4][16];   // [m][ij]
    int t = threadIdx.x;
    if (t < 16) {
        int i = t >> 2, j = t & 3;
        float lg[4];
#pragma unroll
        for (int m = 0; m < 4; m++) {
            float la = 0.f, lb = 0.f;
            for (int o = 0; o < 64; o++) {
                float em = emb_mix[m * 64 + o];
                la += em * emb_a[o * 4 + i];
                lb += em * emb_b[o * 4 + j];
            }
            lg[m] = la + lb;
        }
        float mx = fmaxf(fmaxf(lg[0], lg[1]), fmaxf(lg[2], lg[3]));
        float e[4], s = 0.f;
#pragma unroll
        for (int m = 0; m < 4; m++) { e[m] = expf(lg[m] - mx); s += e[m]; }
#pragma unroll
        for (int m = 0; m < 4; m++) emb[m][t] = e[m] / s;
    }
    __syncthreads();
    for (int idx = t; idx < 1536; idx += blockDim.x) {
        int o = idx / 24, rem = idx % 24, c = rem / 8, p = rem % 8;
#pragma unroll
        for (int s = 0; s < 2; s++) {
            int ij = 2 * p + s;
            float acc = 0.f;
#pragma unroll
            for (int m = 0; m < 4; m++)
                acc += emb[m][ij] * value_w[(m * 64 + o) * 3 + c];
            g_wv[idx * 2 + s] = acc;
        }
    }
}

__global__ __launch_bounds__(128)
void attn_kernel(const float* __restrict__ x,
                 const float* __restrict__ key_w,
                 const float* __restrict__ query_w,
                 float* __restrict__ out) {
    __shared__ float sh_x[3][4][132];  // [c][window row][padded col]
    __shared__ float sh_kw[16 * 3];
    __shared__ float sh_qw[16 * 3];
    __shared__ u64   sh_wv[16 * 3 * 8];

    int tid = threadIdx.x;
    int oq = blockIdx.x & 3;          // which quarter of the 64 channels
    int bh = blockIdx.x >> 2;
    int b = bh >> 7;
    int h = bh & 127;

    // Load padded x tile: original rows h-2..h+1, cols -2..129.
    for (int idx = tid; idx < 3 * 4 * 132; idx += 128) {
        int c = idx / 528, rem = idx % 528, r = rem / 132, cc = rem % 132;
        int hr = h - 2 + r, wc = cc - 2;
        float v = 0.f;
        if (hr >= 0 && hr < 128 && wc >= 0 && wc < 128)
            v = x[((b * 3 + c) * 128 + hr) * 128 + wc];
        sh_x[c][r][cc] = v;
    }
    if (tid < 48) {
        sh_kw[tid] = key_w[oq * 48 + tid];
        sh_qw[tid] = query_w[oq * 48 + tid];
    }
    {
        const u64* gw = (const u64*)g_wv + oq * 384;
        for (int idx = tid; idx < 384; idx += 128) sh_wv[idx] = gw[idx];
    }
    __syncthreads();

    int w = tid;

    // Window into registers, packed by window-position pairs (same i, adjacent j).
    u64 wp[3][8];
    float ctr[3];
#pragma unroll
    for (int c = 0; c < 3; c++) {
#pragma unroll
        for (int p = 0; p < 8; p++) {
            int i = p >> 1, j0 = (p & 1) * 2;
            wp[c][p] = pk2(sh_x[c][i][w + j0], sh_x[c][i][w + j0 + 1]);
        }
        ctr[c] = sh_x[c][2][w + 2];
    }

    float* outp = out + (((b * 64) + oq * 16) * 128 + h) * 128 + w;

#pragma unroll 2
    for (int o = 0; o < 16; o++) {
        float q = sh_qw[o * 3] * ctr[0] + sh_qw[o * 3 + 1] * ctr[1] + sh_qw[o * 3 + 2] * ctr[2];
        q *= LOG2E;
        // Fold q into key weights: logit = (q*k) . window
        float qk0 = q * sh_kw[o * 3];
        float qk1 = q * sh_kw[o * 3 + 1];
        float qk2 = q * sh_kw[o * 3 + 2];
        u64 kw0 = pk2(qk0, qk0);
        u64 kw1 = pk2(qk1, qk1);
        u64 kw2 = pk2(qk2, qk2);
        const u64* wv = sh_wv + o * 24;

        u64 acc = pk2(0.f, 0.f);
        u64 ss  = pk2(0.f, 0.f);
#pragma unroll
        for (int p = 0; p < 8; p++) {
            u64 l2 = fma2_(kw0, wp[0][p], fma2_(kw1, wp[1][p], mul2_(kw2, wp[2][p])));
            float l0, l1; upk2(l2, l0, l1);
            u64 e2 = pk2(ex2_(l0), ex2_(l1));
            u64 v2 = fma2_(wv[p], wp[0][p],
                     fma2_(wv[8 + p], wp[1][p],
                     mul2_(wv[16 + p], wp[2][p])));
            acc = fma2_(e2, v2, acc);
            ss  = add2_(e2, ss);
        }
        float a0, a1, s0, s1;
        upk2(acc, a0, a1);
        upk2(ss, s0, s1);
        outp[o * 16384] = __fdividef(a0 + a1, s0 + s1);
    }
}

extern "C" void kernel_launch(void* const* d_in, const int* in_sizes, int n_in,
                              void* d_out, int out_size) {
    const float* x       = (const float*)d_in[0];
    const float* key_w   = (const float*)d_in[1];
    const float* query_w = (const float*)d_in[2];
    const float* value_w = (const float*)d_in[3];
    const float* emb_a   = (const float*)d_in[4];
    const float* emb_b   = (const float*)d_in[5];
    const float* emb_mix = (const float*)d_in[6];
    float* out = (float*)d_out;

    prep_kernel<<<1, 256>>>(value_w, emb_a, emb_b, emb_mix);
    attn_kernel<<<2048, 128>>>(x, key_w, query_w, out);
}

// round 3
// speedup vs baseline: 1.8630x; 1.0354x over previous
#include <cuda_runtime.h>

// AttentionStem: per-pixel 4x4 local window attention. B=4, IC=3, OC=64, H=W=128.
// R3: fuse prep into attn prologue (kills 10us single-block kernel);
//     force 64 regs (8 CTAs/SM) by aliasing ctr to window regs;
//     vectorize wv/kw/qw shared reads (LDS.128); fold LOG2E into qw.

typedef unsigned long long u64;

#define LOG2E 1.4426950408889634f

__device__ __forceinline__ u64 pk2(float lo, float hi) {
    u64 r; asm("mov.b64 %0,{%1,%2};" : "=l"(r) : "f"(lo), "f"(hi)); return r;
}
__device__ __forceinline__ void upk2(u64 a, float& lo, float& hi) {
    asm("mov.b64 {%0,%1},%2;" : "=f"(lo), "=f"(hi) : "l"(a));
}
__device__ __forceinline__ u64 fma2_(u64 a, u64 b, u64 c) {
    u64 r; asm("fma.rn.f32x2 %0,%1,%2,%3;" : "=l"(r) : "l"(a), "l"(b), "l"(c)); return r;
}
__device__ __forceinline__ u64 mul2_(u64 a, u64 b) {
    u64 r; asm("mul.rn.f32x2 %0,%1,%2;" : "=l"(r) : "l"(a), "l"(b)); return r;
}
__device__ __forceinline__ u64 add2_(u64 a, u64 b) {
    u64 r; asm("add.rn.f32x2 %0,%1,%2;" : "=l"(r) : "l"(a), "l"(b)); return r;
}
__device__ __forceinline__ float ex2_(float x) {
    float r; asm("ex2.approx.f32 %0,%1;" : "=f"(r) : "f"(x)); return r;
}
__device__ __forceinline__ float lo32(u64 a) {
    return __int_as_float((int)(unsigned)a);
}

__global__ __launch_bounds__(128, 8)
void attn_kernel(const float* __restrict__ x,
                 const float* __restrict__ key_w,
                 const float* __restrict__ query_w,
                 const float* __restrict__ value_w,
                 const float* __restrict__ emb_a,
                 const float* __restrict__ emb_b,
                 const float* __restrict__ emb_mix,
                 float* __restrict__ out) {
    __shared__ float  sh_x[3][4][132];   // [c][window row][padded col]
    __shared__ float4 sh_kw[16];
    __shared__ float4 sh_qw[16];         // pre-scaled by LOG2E
    __shared__ u64    sh_wv[16 * 3 * 8]; // [o][c][p]; float view [o*48 + c*16 + ij]
    __shared__ float  sh_lab[32];        // la: [i*4+m], lb: [16 + j*4+m]
    __shared__ float  sh_emb[4][16];     // [m][ij]

    int tid = threadIdx.x;
    int oq = blockIdx.x & 3;             // quarter of the 64 channels
    int bh = blockIdx.x >> 2;
    int b = bh >> 7;
    int h = bh & 127;

    // ---- phase A: x tile, emb dot products, kw/qw ----
    for (int idx = tid; idx < 1584; idx += 128) {
        int c = idx / 528, rem = idx % 528, r = rem / 132, cc = rem % 132;
        int hr = h - 2 + r, wc = cc - 2;
        float v = 0.f;
        if (hr >= 0 && hr < 128 && wc >= 0 && wc < 128)
            v = x[((b * 3 + c) * 128 + hr) * 128 + wc];
        sh_x[c][r][cc] = v;
    }
    if (tid < 32) {
        int m = tid & 3, i4 = (tid >> 2) & 3, ab = tid >> 4;
        const float* e = ab ? emb_b : emb_a;
        float s = 0.f;
        for (int o = 0; o < 64; o++)
            s += emb_mix[m * 64 + o] * e[o * 4 + i4];
        sh_lab[(ab << 4) + (i4 << 2) + m] = s;
    }
    if (tid >= 96 && tid < 112) {
        int o = tid - 96;
        int og = oq * 16 + o;
        sh_kw[o] = make_float4(key_w[og * 3], key_w[og * 3 + 1], key_w[og * 3 + 2], 0.f);
        sh_qw[o] = make_float4(query_w[og * 3] * LOG2E,
                               query_w[og * 3 + 1] * LOG2E,
                               query_w[og * 3 + 2] * LOG2E, 0.f);
    }
    __syncthreads();

    // ---- phase B: softmax over m for each window position ----
    if (tid < 16) {
        int i = tid >> 2, j = tid & 3;
        float lg[4];
#pragma unroll
        for (int m = 0; m < 4; m++)
            lg[m] = sh_lab[(i << 2) + m] + sh_lab[16 + (j << 2) + m];
        float mx = fmaxf(fmaxf(lg[0], lg[1]), fmaxf(lg[2], lg[3]));
        float e[4], s = 0.f;
#pragma unroll
        for (int m = 0; m < 4; m++) { e[m] = __expf(lg[m] - mx); s += e[m]; }
        float inv = __fdividef(1.f, s);
#pragma unroll
        for (int m = 0; m < 4; m++) sh_emb[m][tid] = e[m] * inv;
    }
    __syncthreads();

    // ---- phase C: mixed value weights for this block's 16 channels ----
    {
        float* wvf = (float*)sh_wv;
        for (int f = tid; f < 768; f += 128) {
            int o = f / 48, r = f % 48, c = r >> 4, ij = r & 15;
            int og = oq * 16 + o;
            float acc = 0.f;
#pragma unroll
            for (int m = 0; m < 4; m++)
                acc += sh_emb[m][ij] * value_w[(m * 64 + og) * 3 + c];
            wvf[f] = acc;
        }
    }
    __syncthreads();

    // ---- window into registers, packed by (same i, adjacent j) pairs ----
    int w = tid;
    u64 wp0[8], wp1[8], wp2[8];
#pragma unroll
    for (int p = 0; p < 8; p++) {
        int i = p >> 1, j0 = (p & 1) * 2;
        wp0[p] = pk2(sh_x[0][i][w + j0], sh_x[0][i][w + j0 + 1]);
        wp1[p] = pk2(sh_x[1][i][w + j0], sh_x[1][i][w + j0 + 1]);
        wp2[p] = pk2(sh_x[2][i][w + j0], sh_x[2][i][w + j0 + 1]);
    }

    float* outp = out + (((b * 64) + oq * 16) * 128 + h) * 128 + w;

#pragma unroll 2
    for (int o = 0; o < 16; o++) {
        float4 qw = sh_qw[o];
        // center pixel = low half of pair 5 (i=2, j=2)
        float q = qw.x * lo32(wp0[5]) + qw.y * lo32(wp1[5]) + qw.z * lo32(wp2[5]);
        float4 kw = sh_kw[o];
        float qk0 = q * kw.x, qk1 = q * kw.y, qk2 = q * kw.z;
        u64 k0 = pk2(qk0, qk0), k1 = pk2(qk1, qk1), k2 = pk2(qk2, qk2);
        const u64* wvp = sh_wv + o * 24;

        u64 acc = 0ull, ss = 0ull;
#pragma unroll
        for (int pp = 0; pp < 4; pp++) {
            ulonglong2 wv0 = *(const ulonglong2*)(wvp + 2 * pp);
            ulonglong2 wv1 = *(const ulonglong2*)(wvp + 8 + 2 * pp);
            ulonglong2 wv2 = *(const ulonglong2*)(wvp + 16 + 2 * pp);
            {
                int p = 2 * pp;
                u64 l2 = fma2_(k0, wp0[p], fma2_(k1, wp1[p], mul2_(k2, wp2[p])));
                float l0, l1; upk2(l2, l0, l1);
                u64 e2 = pk2(ex2_(l0), ex2_(l1));
                u64 v2 = fma2_(wv0.x, wp0[p], fma2_(wv1.x, wp1[p], mul2_(wv2.x, wp2[p])));
                acc = fma2_(e2, v2, acc);
                ss  = add2_(e2, ss);
            }
            {
                int p = 2 * pp + 1;
                u64 l2 = fma2_(k0, wp0[p], fma2_(k1, wp1[p], mul2_(k2, wp2[p])));
                float l0, l1; upk2(l2, l0, l1);
                u64 e2 = pk2(ex2_(l0), ex2_(l1));
                u64 v2 = fma2_(wv0.y, wp0[p], fma2_(wv1.y, wp1[p], mul2_(wv2.y, wp2[p])));
                acc = fma2_(e2, v2, acc);
                ss  = add2_(e2, ss);
            }
        }
        float a0, a1, s0, s1;
        upk2(acc, a0, a1);
        upk2(ss, s0, s1);
        outp[o * 16384] = __fdividef(a0 + a1, s0 + s1);
    }
}

extern "C" void kernel_launch(void* const* d_in, const int* in_sizes, int n_in,
                              void* d_out, int out_size) {
    const float* x       = (const float*)d_in[0];
    const float* key_w   = (const float*)d_in[1];
    const float* query_w = (const float*)d_in[2];
    const float* value_w = (const float*)d_in[3];
    const float* emb_a   = (const float*)d_in[4];
    const float* emb_b   = (const float*)d_in[5];
    const float* emb_mix = (const float*)d_in[6];
    float* out = (float*)d_out;

    attn_kernel<<<2048, 128>>>(x, key_w, query_w, value_w, emb_a, emb_b, emb_mix, out);
}